// round 12
// baseline (speedup 1.0000x reference)
#include <cuda_runtime.h>

#define MAXN 512
#define NSLICE 4
#define SPECIAL_ATOM 8

typedef unsigned long long ull;

__device__ float g_part[MAXN][NSLICE];
__device__ int   g_cnt[MAXN];          // zero-initialized; self-resetting

__device__ __forceinline__ float warp_sum(float v) {
    v += __shfl_down_sync(0xffffffffu, v, 16);
    v += __shfl_down_sync(0xffffffffu, v, 8);
    v += __shfl_down_sync(0xffffffffu, v, 4);
    v += __shfl_down_sync(0xffffffffu, v, 2);
    v += __shfl_down_sync(0xffffffffu, v, 1);
    return v;
}

__device__ __forceinline__ float fast_lg2(float x) {
    float r; asm("lg2.approx.ftz.f32 %0, %1;" : "=f"(r) : "f"(x)); return r;
}
__device__ __forceinline__ float fast_ex2(float x) {
    float r; asm("ex2.approx.ftz.f32 %0, %1;" : "=f"(r) : "f"(x)); return r;
}

// ---- packed f32x2 helpers ----
__device__ __forceinline__ ull pack2(float lo, float hi) {
    ull r; asm("mov.b64 %0, {%1, %2};" : "=l"(r) : "f"(lo), "f"(hi)); return r;
}
__device__ __forceinline__ ull dup2(float v) {
    ull r; asm("mov.b64 %0, {%1, %1};" : "=l"(r) : "f"(v)); return r;
}
__device__ __forceinline__ void unpack2(ull v, float& lo, float& hi) {
    asm("mov.b64 {%0, %1}, %2;" : "=f"(lo), "=f"(hi) : "l"(v));
}
__device__ __forceinline__ ull fma2(ull a, ull b, ull c) {
    ull d; asm("fma.rn.f32x2 %0, %1, %2, %3;" : "=l"(d) : "l"(a), "l"(b), "l"(c)); return d;
}
__device__ __forceinline__ ull mul2(ull a, ull b) {
    ull d; asm("mul.rn.f32x2 %0, %1, %2;" : "=l"(d) : "l"(a), "l"(b)); return d;
}
__device__ __forceinline__ ull add2(ull a, ull b) {
    ull d; asm("add.rn.f32x2 %0, %1, %2;" : "=l"(d) : "l"(a), "l"(b)); return d;
}

__device__ __forceinline__ float fc_poly(float s) {
    float p = -2.133e-10f;
    p = fmaf(p, s, 7.00553e-8f);
    p = fmaf(p, s, -1.430964e-5f);
    p = fmaf(p, s, 1.565855e-3f);
    p = fmaf(p, s, -6.8538918e-2f);
    p = fmaf(p, s, 1.0f);
    return p;
}

// Each CTA = (atom i, slice s). Compaction -> pipelined sliced triplet loop ->
// partial store; the last-arriving slice combines deterministically + MLP.
__global__ __launch_bounds__(256, 3) void fused_kernel(
    const float* __restrict__ x, int N,
    const float* __restrict__ w1a, const float* __restrict__ b1a,
    const float* __restrict__ w2a, const float* __restrict__ b2a,
    const float* __restrict__ w3a, const float* __restrict__ b3a,
    const float* __restrict__ w1b, const float* __restrict__ b1b,
    const float* __restrict__ w2b, const float* __restrict__ b2b,
    const float* __restrict__ w3b, const float* __restrict__ b3b,
    float* __restrict__ out)
{
    const int i  = blockIdx.x >> 2;        // atom
    const int sl = blockIdx.x & 3;         // slice
    __shared__ float4 sU[MAXN + 32];
    __shared__ float2 sB[MAXN + 32];
    __shared__ float  sW[1841];
    __shared__ int    cnt[16], off[16];
    __shared__ float  red[8], wr[8];
    __shared__ int    Msh, isLastSh;
    __shared__ float  sRad, sAng, sH1[40], sH2[40];

    const int tid  = threadIdx.x;
    const int lane = tid & 31;
    const int w    = tid >> 5;

    const float xi0 = x[3 * i], xi1 = x[3 * i + 1], xi2 = x[3 * i + 2];

    // --- phase 1: 8 warps x 2 passes cover 16 chunks of 32 atoms ---
    bool  ev[2];  int erank[2];
    float eux[2], euy[2], euz[2], eD[2], eD2[2], ea[2];
    float rad = 0.f;
    #pragma unroll
    for (int pass = 0; pass < 2; pass++) {
        const int c = w + 8 * pass;
        const int j = c * 32 + lane;
        float dx = 0.f, dy = 0.f, dz = 0.f, D2 = 1e9f;
        bool valid = false;
        if (j < N) {
            dx = xi0 - x[3 * j];
            dy = xi1 - x[3 * j + 1];
            dz = xi2 - x[3 * j + 2];
            D2 = fmaf(dx, dx, fmaf(dy, dy, dz * dz));
            valid = (j != i) && (D2 <= 36.f);
        }
        unsigned mask = __ballot_sync(0xffffffffu, valid);
        ev[pass] = valid;
        erank[pass] = __popc(mask & ((1u << lane) - 1u));
        if (valid) {
            float inv = rsqrtf(D2);
            float D = D2 * inv;
            float fc = fmaf(0.5f, __cosf(0.5235987755982988f * D), 0.5f);
            float a = __expf(-0.5f * D2) * fc;     // ETA = 0.5
            float dm = D - 1.f;                     // RS = 1
            rad += __expf(-0.5f * dm * dm) * fc;
            eux[pass] = dx * inv; euy[pass] = dy * inv; euz[pass] = dz * inv;
            eD[pass] = D; eD2[pass] = D2; ea[pass] = a;
        }
        if (lane == 0) cnt[c] = __popc(mask);
    }
    rad = warp_sum(rad);
    if (lane == 0) red[w] = rad;
    __syncthreads();

    // --- phase 2: prefix scan + radial total ---
    if (tid < 16) {
        int c = cnt[tid];
        int cs = c;
        #pragma unroll
        for (int d = 1; d < 16; d <<= 1) {
            int t = __shfl_up_sync(0xffffu, cs, d);
            if (tid >= d) cs += t;
        }
        off[tid] = cs - c;
        if (tid == 15) Msh = cs;
        if (tid < 8) {
            float r = red[tid];
            #pragma unroll
            for (int d = 4; d >= 1; d >>= 1) r += __shfl_down_sync(0xffu, r, d);
            if (tid == 0) sRad = r;
        }
    }
    __syncthreads();

    // --- phase 3: scatter + sentinels ---
    #pragma unroll
    for (int pass = 0; pass < 2; pass++) {
        if (ev[pass]) {
            int pos = off[w + 8 * pass] + erank[pass];
            sU[pos] = make_float4(eux[pass], euy[pass], euz[pass], eD[pass]);
            sB[pos] = make_float2(eD2[pass], ea[pass]);
        }
    }
    const int M = Msh;
    const int Mpad = ((M >> 5) + 1) << 5;      // >= M+1 sentinels
    if (tid < Mpad - M) {
        sU[M + tid] = make_float4(0.f, 0.f, 0.f, 1e3f);
        sB[M + tid] = make_float2(1e6f, 0.f);
    }
    __syncthreads();

    const ull K1   = dup2(1.0f);
    const ull KN08 = dup2(-0.8f);
    const ull K06  = dup2(0.6f);
    const ull KNE  = dup2(-0.72134752044448f);
    const ull PC5  = dup2(-2.133e-10f);
    const ull PC4  = dup2(7.00553e-8f);
    const ull PC3  = dup2(-1.430964e-5f);
    const ull PC2  = dup2(1.565855e-3f);
    const ull PC1  = dup2(-6.8538918e-2f);

    // --- phase 4: sliced 4-row blocks, software-pipelined k-tile loop ---
    float accw = 0.f;
    for (int blk = 4 * w + sl; 4 * blk < M; blk += 32) {
        const int j0 = 4 * blk;
        const int j1 = (j0 + 1 < M) ? j0 + 1 : M;
        const int j2 = (j0 + 2 < M) ? j0 + 2 : M;
        const int j3 = (j0 + 3 < M) ? j0 + 3 : M;
        const float4 u0 = sU[j0], u1 = sU[j1], u2 = sU[j2], u3 = sU[j3];
        const float2 b0 = sB[j0], b1 = sB[j1], b2 = sB[j2], b3 = sB[j3];

        const ull uxA = pack2(u0.x, u1.x), uxB = pack2(u2.x, u3.x);
        const ull uyA = pack2(u0.y, u1.y), uyB = pack2(u2.y, u3.y);
        const ull uzA = pack2(u0.z, u1.z), uzB = pack2(u2.z, u3.z);
        const ull cA  = pack2(-2.f * u0.w, -2.f * u1.w);
        const ull cB  = pack2(-2.f * u2.w, -2.f * u3.w);
        const ull sA  = pack2(b0.x, b1.x), sB2 = pack2(b2.x, b3.x);
        ull accA = 0, accB = 0;

        const int t0 = j0 & ~31;
        {   // peel tile (scalar, predicated)
            const int kk = t0 + lane;
            float4 uk = sU[kk]; float2 bk = sB[kk];
            float aa0 = 0.f, aa1 = 0.f, aa2 = 0.f, aa3 = 0.f;
            float d, t, q, P;
            d = fmaf(u0.x, uk.x, fmaf(u0.y, uk.y, u0.z * uk.z));
            t = fmaf(-0.8f, d, 1.0f);
            q = fmaf(-2.f * u0.w * uk.w, d, b0.x + bk.x);
            P = fast_ex2(fmaf(-0.72134752044448f, q, 0.6f * fast_lg2(t)));
            if (kk > j0) aa0 = P * fc_poly(q) * bk.y;
            d = fmaf(u1.x, uk.x, fmaf(u1.y, uk.y, u1.z * uk.z));
            t = fmaf(-0.8f, d, 1.0f);
            q = fmaf(-2.f * u1.w * uk.w, d, b1.x + bk.x);
            P = fast_ex2(fmaf(-0.72134752044448f, q, 0.6f * fast_lg2(t)));
            if (kk > j1) aa1 = P * fc_poly(q) * bk.y;
            d = fmaf(u2.x, uk.x, fmaf(u2.y, uk.y, u2.z * uk.z));
            t = fmaf(-0.8f, d, 1.0f);
            q = fmaf(-2.f * u2.w * uk.w, d, b2.x + bk.x);
            P = fast_ex2(fmaf(-0.72134752044448f, q, 0.6f * fast_lg2(t)));
            if (kk > j2) aa2 = P * fc_poly(q) * bk.y;
            d = fmaf(u3.x, uk.x, fmaf(u3.y, uk.y, u3.z * uk.z));
            t = fmaf(-0.8f, d, 1.0f);
            q = fmaf(-2.f * u3.w * uk.w, d, b3.x + bk.x);
            P = fast_ex2(fmaf(-0.72134752044448f, q, 0.6f * fast_lg2(t)));
            if (kk > j3) aa3 = P * fc_poly(q) * bk.y;
            accA = pack2(aa0, aa1);
            accB = pack2(aa2, aa3);
        }

        // packed tile computation (consumes prefetched uk/bk)
        auto body = [&](const float4& uk, const float2& bk) {
            const ull ukx = dup2(uk.x), uky = dup2(uk.y), ukz = dup2(uk.z);
            const ull ukw = dup2(uk.w), bkx = dup2(bk.x), bky = dup2(bk.y);
            float lo, hi;
            ull dotA = fma2(uxA, ukx, fma2(uyA, uky, mul2(uzA, ukz)));
            ull tA   = fma2(KN08, dotA, K1);
            ull qA   = fma2(mul2(cA, ukw), dotA, add2(sA, bkx));
            unpack2(tA, lo, hi);
            ull lgA  = pack2(fast_lg2(lo), fast_lg2(hi));
            ull zA   = fma2(K06, lgA, mul2(KNE, qA));
            unpack2(zA, lo, hi);
            ull PA   = pack2(fast_ex2(lo), fast_ex2(hi));
            ull pA   = fma2(PC5, qA, PC4);
            pA = fma2(pA, qA, PC3);
            pA = fma2(pA, qA, PC2);
            pA = fma2(pA, qA, PC1);
            pA = fma2(pA, qA, K1);
            accA = fma2(mul2(PA, pA), bky, accA);
            ull dotB = fma2(uxB, ukx, fma2(uyB, uky, mul2(uzB, ukz)));
            ull tB   = fma2(KN08, dotB, K1);
            ull qB   = fma2(mul2(cB, ukw), dotB, add2(sB2, bkx));
            unpack2(tB, lo, hi);
            ull lgB  = pack2(fast_lg2(lo), fast_lg2(hi));
            ull zB   = fma2(K06, lgB, mul2(KNE, qB));
            unpack2(zB, lo, hi);
            ull PB   = pack2(fast_ex2(lo), fast_ex2(hi));
            ull pB   = fma2(PC5, qB, PC4);
            pB = fma2(pB, qB, PC3);
            pB = fma2(pB, qB, PC2);
            pB = fma2(pB, qB, PC1);
            pB = fma2(pB, qB, K1);
            accB = fma2(mul2(PB, pB), bky, accB);
        };

        // software-pipelined clean tiles: prefetch next tile before computing current
        int tt = t0 + 32;
        if (tt < Mpad) {
            float4 uk = sU[tt + lane];
            float2 bk = sB[tt + lane];
            #pragma unroll 2
            for (; tt + 32 < Mpad; tt += 32) {
                float4 ukn = sU[tt + 32 + lane];
                float2 bkn = sB[tt + 32 + lane];
                body(uk, bk);
                uk = ukn; bk = bkn;
            }
            body(uk, bk);
        }

        float a0, a1, a2, a3;
        unpack2(accA, a0, a1);
        unpack2(accB, a2, a3);
        accw = fmaf(b0.y, a0, accw);
        accw = fmaf(b1.y, a1, accw);
        accw = fmaf(b2.y, a2, accw);
        accw = fmaf(b3.y, a3, accw);
    }

    accw = warp_sum(accw);
    if (lane == 0) wr[w] = accw;
    __syncthreads();

    // --- publish slice partial; elect last-arriving CTA of this atom ---
    if (tid == 0) {
        float ssum = 0.f;
        #pragma unroll
        for (int q = 0; q < 8; q++) ssum += wr[q];
        g_part[i][sl] = ssum;
        __threadfence();
        int old = atomicAdd(&g_cnt[i], 1);
        int last = (old == NSLICE - 1);
        isLastSh = last;
        if (last) g_cnt[i] = 0;   // reset for next launch / graph replay
    }
    __syncthreads();
    if (!isLastSh) return;

    // --- last CTA: stage weights, deterministic combine, fused MLP ---
    const bool sp = (i == SPECIAL_ATOM);
    const float* W1 = sp ? w1b : w1a;  const float* B1 = sp ? b1b : b1a;
    const float* W2 = sp ? w2b : w2a;  const float* B2 = sp ? b2b : b2a;
    const float* W3 = sp ? w3b : w3a;  const float* B3 = sp ? b3b : b3a;
    for (int t = tid; t < 1841; t += 256) {
        float v;
        if (t < 80)        v = W1[t];
        else if (t < 120)  v = B1[t - 80];
        else if (t < 1760) { int r = (t - 120) / 41, c = (t - 120) - 41 * r;
                             v = (c < 40) ? W2[r * 40 + c] : 0.f; }
        else if (t < 1800) v = B2[t - 1760];
        else if (t < 1840) v = W3[t - 1800];
        else               v = B3[0];
        sW[t] = v;
    }
    if (tid == 0) {
        float s4 = 0.f;
        #pragma unroll
        for (int q = 0; q < NSLICE; q++) s4 += __ldcg(&g_part[i][q]);  // fixed order
        sAng = 1.3195079107728942f * s4;   // 2^(1-ZETA)
    }
    __syncthreads();

    if (tid < 40) {
        float z = fmaf(sW[2 * tid], sAng, fmaf(sW[2 * tid + 1], sRad, sW[80 + tid]));
        sH1[tid] = __fdividef(1.f, fmaf(z, z, 1.f));
    }
    __syncthreads();
    if (tid < 40) {
        float z = sW[1760 + tid];
        const float* row = sW + 120 + tid * 41;
        #pragma unroll 8
        for (int k = 0; k < 40; k++) z = fmaf(row[k], sH1[k], z);
        sH2[tid] = __fdividef(1.f, fmaf(z, z, 1.f));
    }
    __syncthreads();
    if (w == 0) {
        float v = sW[1800 + lane] * sH2[lane];
        if (lane < 8) v = fmaf(sW[1832 + lane], sH2[32 + lane], v);
        v = warp_sum(v);
        if (lane == 0) out[i] = v + sW[1840];
    }
}

extern "C" void kernel_launch(void* const* d_in, const int* in_sizes, int n_in,
                              void* d_out, int out_size) {
    const float* x = (const float*)d_in[0];
    const int N = in_sizes[0] / 3;

    fused_kernel<<<NSLICE * N, 256>>>(
        x, N,
        (const float*)d_in[1],  (const float*)d_in[2],  (const float*)d_in[3],
        (const float*)d_in[4],  (const float*)d_in[5],  (const float*)d_in[6],
        (const float*)d_in[7],  (const float*)d_in[8],  (const float*)d_in[9],
        (const float*)d_in[10], (const float*)d_in[11], (const float*)d_in[12],
        (float*)d_out);
}

// round 13
// speedup vs baseline: 1.2634x; 1.2634x over previous
#include <cuda_runtime.h>

#define MAXN 512
#define NSLICE 4
#define SPECIAL_ATOM 8

__device__ float g_part[MAXN][NSLICE];
__device__ int   g_cnt[MAXN];          // zero-initialized; self-resetting

__device__ __forceinline__ float warp_sum(float v) {
    v += __shfl_down_sync(0xffffffffu, v, 16);
    v += __shfl_down_sync(0xffffffffu, v, 8);
    v += __shfl_down_sync(0xffffffffu, v, 4);
    v += __shfl_down_sync(0xffffffffu, v, 2);
    v += __shfl_down_sync(0xffffffffu, v, 1);
    return v;
}

__device__ __forceinline__ float fast_lg2(float x) {
    float r; asm("lg2.approx.ftz.f32 %0, %1;" : "=f"(r) : "f"(x)); return r;
}
__device__ __forceinline__ float fast_ex2(float x) {
    float r; asm("ex2.approx.ftz.f32 %0, %1;" : "=f"(r) : "f"(x)); return r;
}

// fc(D)=0.5*(cos(pi*D/6)+1) deg-5 Taylor in s=D^2; error weighted by the
// fused exp(-0.7213*s) factor stays <~1e-6 everywhere it matters.
__device__ __forceinline__ float fc_poly(float s) {
    float p = -2.133e-10f;
    p = fmaf(p, s, 7.00553e-8f);
    p = fmaf(p, s, -1.430964e-5f);
    p = fmaf(p, s, 1.565855e-3f);
    p = fmaf(p, s, -6.8538918e-2f);
    p = fmaf(p, s, 1.0f);
    return p;
}

// Each CTA = (atom i, slice s). Compaction -> scalar 2-row triplet loop ->
// partial store; last-arriving slice combines deterministically + MLP.
// launch_bounds(256,5): <=51 regs -> 5 CTAs/SM -> 40 resident warps.
__global__ __launch_bounds__(256, 5) void fused_kernel(
    const float* __restrict__ x, int N,
    const float* __restrict__ w1a, const float* __restrict__ b1a,
    const float* __restrict__ w2a, const float* __restrict__ b2a,
    const float* __restrict__ w3a, const float* __restrict__ b3a,
    const float* __restrict__ w1b, const float* __restrict__ b1b,
    const float* __restrict__ w2b, const float* __restrict__ b2b,
    const float* __restrict__ w3b, const float* __restrict__ b3b,
    float* __restrict__ out)
{
    const int i  = blockIdx.x >> 2;        // atom
    const int sl = blockIdx.x & 3;         // slice
    __shared__ float4 sU[MAXN + 32];       // {ux, uy, uz, D}
    __shared__ float2 sB[MAXN + 32];       // {D^2, a_ij}
    __shared__ float  sW[1841];
    __shared__ int    cnt[16], off[16];
    __shared__ float  red[8], wr[8];
    __shared__ int    Msh, isLastSh;
    __shared__ float  sRad, sAng, sH1[40], sH2[40];

    const int tid  = threadIdx.x;
    const int lane = tid & 31;
    const int w    = tid >> 5;

    const float xi0 = x[3 * i], xi1 = x[3 * i + 1], xi2 = x[3 * i + 2];

    // --- phase 1: 8 warps x 2 passes cover 16 chunks of 32 atoms ---
    bool  ev[2];  int erank[2];
    float eux[2], euy[2], euz[2], eD[2], eD2[2], ea[2];
    float rad = 0.f;
    #pragma unroll
    for (int pass = 0; pass < 2; pass++) {
        const int c = w + 8 * pass;
        const int j = c * 32 + lane;
        float dx = 0.f, dy = 0.f, dz = 0.f, D2 = 1e9f;
        bool valid = false;
        if (j < N) {
            dx = xi0 - x[3 * j];
            dy = xi1 - x[3 * j + 1];
            dz = xi2 - x[3 * j + 2];
            D2 = fmaf(dx, dx, fmaf(dy, dy, dz * dz));
            valid = (j != i) && (D2 <= 36.f);
        }
        unsigned mask = __ballot_sync(0xffffffffu, valid);
        ev[pass] = valid;
        erank[pass] = __popc(mask & ((1u << lane) - 1u));
        if (valid) {
            float inv = rsqrtf(D2);
            float D = D2 * inv;
            float fc = fmaf(0.5f, __cosf(0.5235987755982988f * D), 0.5f);
            float a = __expf(-0.5f * D2) * fc;     // ETA = 0.5
            float dm = D - 1.f;                     // RS = 1
            rad += __expf(-0.5f * dm * dm) * fc;
            eux[pass] = dx * inv; euy[pass] = dy * inv; euz[pass] = dz * inv;
            eD[pass] = D; eD2[pass] = D2; ea[pass] = a;
        }
        if (lane == 0) cnt[c] = __popc(mask);
    }
    rad = warp_sum(rad);
    if (lane == 0) red[w] = rad;
    __syncthreads();

    // --- phase 2: prefix scan + radial total ---
    if (tid < 16) {
        int c = cnt[tid];
        int cs = c;
        #pragma unroll
        for (int d = 1; d < 16; d <<= 1) {
            int t = __shfl_up_sync(0xffffu, cs, d);
            if (tid >= d) cs += t;
        }
        off[tid] = cs - c;
        if (tid == 15) Msh = cs;
        if (tid < 8) {
            float r = red[tid];
            #pragma unroll
            for (int d = 4; d >= 1; d >>= 1) r += __shfl_down_sync(0xffu, r, d);
            if (tid == 0) sRad = r;
        }
    }
    __syncthreads();

    // --- phase 3: scatter + sentinels ---
    #pragma unroll
    for (int pass = 0; pass < 2; pass++) {
        if (ev[pass]) {
            int pos = off[w + 8 * pass] + erank[pass];
            sU[pos] = make_float4(eux[pass], euy[pass], euz[pass], eD[pass]);
            sB[pos] = make_float2(eD2[pass], ea[pass]);
        }
    }
    const int M = Msh;
    const int Mpad = ((M >> 5) + 1) << 5;      // >= M+1 sentinels
    if (tid < Mpad - M) {
        sU[M + tid] = make_float4(0.f, 0.f, 0.f, 1e3f);
        sB[M + tid] = make_float2(1e6f, 0.f);  // a = 0 -> zero contribution
    }
    __syncthreads();

    // --- phase 4: scalar 2-row triplet loop; stream = 4w + sl, stride 32 pairs ---
    float accw = 0.f;
    for (int p = 4 * w + sl; 2 * p < M; p += 32) {
        const int j0 = 2 * p;
        const int j1 = j0 + 1;                 // j1 <= M; index M is the a=0 sentinel
        const float4 u0 = sU[j0], u1 = sU[j1];
        const float2 b0 = sB[j0], b1 = sB[j1];
        const float cn0 = -2.f * u0.w, s0 = b0.x;
        const float cn1 = -2.f * u1.w, s1 = b1.x;
        float acc0 = 0.f, acc1 = 0.f;

        const int t0 = j0 & ~31;               // tile containing j0 and j1
        {   // peel tile (predicated)
            const int kk = t0 + lane;
            float4 uk = sU[kk]; float2 bk = sB[kk];
            float d, t, q, P;
            d = fmaf(u0.x, uk.x, fmaf(u0.y, uk.y, u0.z * uk.z));
            t = fmaf(-0.8f, d, 1.0f);
            q = fmaf(cn0 * uk.w, d, s0 + bk.x);
            P = fast_ex2(fmaf(-0.72134752044448f, q, 0.6f * fast_lg2(t)));
            if (kk > j0) acc0 = fmaf(P * fc_poly(q), bk.y, acc0);
            d = fmaf(u1.x, uk.x, fmaf(u1.y, uk.y, u1.z * uk.z));
            t = fmaf(-0.8f, d, 1.0f);
            q = fmaf(cn1 * uk.w, d, s1 + bk.x);
            P = fast_ex2(fmaf(-0.72134752044448f, q, 0.6f * fast_lg2(t)));
            if (kk > j1) acc1 = fmaf(P * fc_poly(q), bk.y, acc1);
        }
        // clean tiles
        #pragma unroll 2
        for (int tt = t0 + 32; tt < Mpad; tt += 32) {
            const int kk = tt + lane;
            float4 uk = sU[kk]; float2 bk = sB[kk];
            float d, t, q, P;
            d = fmaf(u0.x, uk.x, fmaf(u0.y, uk.y, u0.z * uk.z));
            t = fmaf(-0.8f, d, 1.0f);
            q = fmaf(cn0 * uk.w, d, s0 + bk.x);
            P = fast_ex2(fmaf(-0.72134752044448f, q, 0.6f * fast_lg2(t)));
            acc0 = fmaf(P * fc_poly(q), bk.y, acc0);
            d = fmaf(u1.x, uk.x, fmaf(u1.y, uk.y, u1.z * uk.z));
            t = fmaf(-0.8f, d, 1.0f);
            q = fmaf(cn1 * uk.w, d, s1 + bk.x);
            P = fast_ex2(fmaf(-0.72134752044448f, q, 0.6f * fast_lg2(t)));
            acc1 = fmaf(P * fc_poly(q), bk.y, acc1);
        }
        accw = fmaf(b0.y, acc0, accw);
        accw = fmaf(b1.y, acc1, accw);         // b1.y = 0 for sentinel row
    }

    accw = warp_sum(accw);
    if (lane == 0) wr[w] = accw;
    __syncthreads();

    // --- publish slice partial; elect last-arriving CTA of this atom ---
    if (tid == 0) {
        float ssum = 0.f;
        #pragma unroll
        for (int q = 0; q < 8; q++) ssum += wr[q];
        g_part[i][sl] = ssum;
        __threadfence();
        int old = atomicAdd(&g_cnt[i], 1);
        int last = (old == NSLICE - 1);
        isLastSh = last;
        if (last) g_cnt[i] = 0;   // reset for next launch / graph replay
    }
    __syncthreads();
    if (!isLastSh) return;

    // --- last CTA: stage weights, deterministic combine, fused MLP ---
    const bool sp = (i == SPECIAL_ATOM);
    const float* W1 = sp ? w1b : w1a;  const float* B1 = sp ? b1b : b1a;
    const float* W2 = sp ? w2b : w2a;  const float* B2 = sp ? b2b : b2a;
    const float* W3 = sp ? w3b : w3a;  const float* B3 = sp ? b3b : b3a;
    for (int t = tid; t < 1841; t += 256) {
        float v;
        if (t < 80)        v = W1[t];
        else if (t < 120)  v = B1[t - 80];
        else if (t < 1760) { int r = (t - 120) / 41, c = (t - 120) - 41 * r;
                             v = (c < 40) ? W2[r * 40 + c] : 0.f; }
        else if (t < 1800) v = B2[t - 1760];
        else if (t < 1840) v = W3[t - 1800];
        else               v = B3[0];
        sW[t] = v;
    }
    if (tid == 0) {
        float s4 = 0.f;
        #pragma unroll
        for (int q = 0; q < NSLICE; q++) s4 += __ldcg(&g_part[i][q]);  // fixed order
        sAng = 1.3195079107728942f * s4;   // 2^(1-ZETA)
    }
    __syncthreads();

    if (tid < 40) {
        float z = fmaf(sW[2 * tid], sAng, fmaf(sW[2 * tid + 1], sRad, sW[80 + tid]));
        sH1[tid] = __fdividef(1.f, fmaf(z, z, 1.f));
    }
    __syncthreads();
    if (tid < 40) {
        float z = sW[1760 + tid];
        const float* row = sW + 120 + tid * 41;
        #pragma unroll 8
        for (int k = 0; k < 40; k++) z = fmaf(row[k], sH1[k], z);
        sH2[tid] = __fdividef(1.f, fmaf(z, z, 1.f));
    }
    __syncthreads();
    if (w == 0) {
        float v = sW[1800 + lane] * sH2[lane];
        if (lane < 8) v = fmaf(sW[1832 + lane], sH2[32 + lane], v);
        v = warp_sum(v);
        if (lane == 0) out[i] = v + sW[1840];
    }
}

extern "C" void kernel_launch(void* const* d_in, const int* in_sizes, int n_in,
                              void* d_out, int out_size) {
    const float* x = (const float*)d_in[0];
    const int N = in_sizes[0] / 3;

    fused_kernel<<<NSLICE * N, 256>>>(
        x, N,
        (const float*)d_in[1],  (const float*)d_in[2],  (const float*)d_in[3],
        (const float*)d_in[4],  (const float*)d_in[5],  (const float*)d_in[6],
        (const float*)d_in[7],  (const float*)d_in[8],  (const float*)d_in[9],
        (const float*)d_in[10], (const float*)d_in[11], (const float*)d_in[12],
        (float*)d_out);
}

// round 14
// speedup vs baseline: 1.3566x; 1.0737x over previous
#include <cuda_runtime.h>

#define MAXN 512
#define NSLICE 4
#define SPECIAL_ATOM 8

__device__ float g_part[MAXN][NSLICE];
__device__ int   g_cnt[MAXN];          // zero-initialized; self-resetting

__device__ __forceinline__ float warp_sum(float v) {
    v += __shfl_down_sync(0xffffffffu, v, 16);
    v += __shfl_down_sync(0xffffffffu, v, 8);
    v += __shfl_down_sync(0xffffffffu, v, 4);
    v += __shfl_down_sync(0xffffffffu, v, 2);
    v += __shfl_down_sync(0xffffffffu, v, 1);
    return v;
}

__device__ __forceinline__ float fast_lg2(float x) {
    float r; asm("lg2.approx.ftz.f32 %0, %1;" : "=f"(r) : "f"(x)); return r;
}
__device__ __forceinline__ float fast_ex2(float x) {
    float r; asm("ex2.approx.ftz.f32 %0, %1;" : "=f"(r) : "f"(x)); return r;
}

// fc(D)=0.5*(cos(pi*D/6)+1) deg-5 Taylor in s=D^2; error weighted by the
// fused exp(-0.7213*s) factor stays <~1e-6 everywhere it matters.
__device__ __forceinline__ float fc_poly(float s) {
    float p = -2.133e-10f;
    p = fmaf(p, s, 7.00553e-8f);
    p = fmaf(p, s, -1.430964e-5f);
    p = fmaf(p, s, 1.565855e-3f);
    p = fmaf(p, s, -6.8538918e-2f);
    p = fmaf(p, s, 1.0f);
    return p;
}

// Each CTA = (atom i, slice sl). Compaction -> 4-row zigzag triplet loop
// (a_ik folded into EX2 via stored lg2(a)) -> partial; last slice does MLP.
__global__ __launch_bounds__(256, 4) void fused_kernel(
    const float* __restrict__ x, int N,
    const float* __restrict__ w1a, const float* __restrict__ b1a,
    const float* __restrict__ w2a, const float* __restrict__ b2a,
    const float* __restrict__ w3a, const float* __restrict__ b3a,
    const float* __restrict__ w1b, const float* __restrict__ b1b,
    const float* __restrict__ w2b, const float* __restrict__ b2b,
    const float* __restrict__ w3b, const float* __restrict__ b3b,
    float* __restrict__ out)
{
    const int i  = blockIdx.x >> 2;        // atom
    const int sl = blockIdx.x & 3;         // slice
    __shared__ float4 sU[MAXN + 32];       // {ux, uy, uz, D}
    __shared__ float2 sB[MAXN + 32];       // {D^2, lg2(a_ij)}
    __shared__ float  sW[1841];
    __shared__ int    cnt[16], off[16];
    __shared__ float  red[8], wr[8];
    __shared__ int    Msh, isLastSh;
    __shared__ float  sRad, sAng, sH1[40], sH2[40];

    const int tid  = threadIdx.x;
    const int lane = tid & 31;
    const int w    = tid >> 5;

    const float xi0 = x[3 * i], xi1 = x[3 * i + 1], xi2 = x[3 * i + 2];
    const float NEGINF = __int_as_float(0xff800000);

    // --- phase 1: 8 warps x 2 passes cover 16 chunks of 32 atoms ---
    bool  ev[2];  int erank[2];
    float eux[2], euy[2], euz[2], eD[2], eD2[2], elg[2];
    float rad = 0.f;
    #pragma unroll
    for (int pass = 0; pass < 2; pass++) {
        const int c = w + 8 * pass;
        const int j = c * 32 + lane;
        float dx = 0.f, dy = 0.f, dz = 0.f, D2 = 1e9f;
        bool valid = false;
        if (j < N) {
            dx = xi0 - x[3 * j];
            dy = xi1 - x[3 * j + 1];
            dz = xi2 - x[3 * j + 2];
            D2 = fmaf(dx, dx, fmaf(dy, dy, dz * dz));
            valid = (j != i) && (D2 <= 36.f);
        }
        unsigned mask = __ballot_sync(0xffffffffu, valid);
        ev[pass] = valid;
        erank[pass] = __popc(mask & ((1u << lane) - 1u));
        if (valid) {
            float inv = rsqrtf(D2);
            float D = D2 * inv;
            float fc = fmaf(0.5f, __cosf(0.5235987755982988f * D), 0.5f);
            float a = __expf(-0.5f * D2) * fc;     // ETA = 0.5
            float dm = D - 1.f;                     // RS = 1
            rad += __expf(-0.5f * dm * dm) * fc;
            eux[pass] = dx * inv; euy[pass] = dy * inv; euz[pass] = dz * inv;
            eD[pass] = D; eD2[pass] = D2;
            elg[pass] = fast_lg2(a);               // -inf when a==0 (boundary)
        }
        if (lane == 0) cnt[c] = __popc(mask);
    }
    rad = warp_sum(rad);
    if (lane == 0) red[w] = rad;
    __syncthreads();

    // --- phase 2: prefix scan + radial total ---
    if (tid < 16) {
        int c = cnt[tid];
        int cs = c;
        #pragma unroll
        for (int d = 1; d < 16; d <<= 1) {
            int t = __shfl_up_sync(0xffffu, cs, d);
            if (tid >= d) cs += t;
        }
        off[tid] = cs - c;
        if (tid == 15) Msh = cs;
        if (tid < 8) {
            float r = red[tid];
            #pragma unroll
            for (int d = 4; d >= 1; d >>= 1) r += __shfl_down_sync(0xffu, r, d);
            if (tid == 0) sRad = r;
        }
    }
    __syncthreads();

    // --- phase 3: scatter + sentinels ---
    #pragma unroll
    for (int pass = 0; pass < 2; pass++) {
        if (ev[pass]) {
            int pos = off[w + 8 * pass] + erank[pass];
            sU[pos] = make_float4(eux[pass], euy[pass], euz[pass], eD[pass]);
            sB[pos] = make_float2(eD2[pass], elg[pass]);
        }
    }
    const int M = Msh;
    const int Mpad = ((M >> 5) + 1) << 5;      // >= M+1 sentinels
    if (tid < Mpad - M) {
        sU[M + tid] = make_float4(0.f, 0.f, 0.f, 1e3f);
        sB[M + tid] = make_float2(1e6f, NEGINF);  // lg(a)=-inf -> exact 0
    }
    __syncthreads();

    // --- phase 4: 4-row blocks, zigzag stream mapping over rounds ---
    const int strm = 4 * w + sl;               // 0..31
    float accw = 0.f;
    for (int t4 = 0; 128 * t4 < M; t4++) {
        const int blk = 32 * t4 + ((t4 & 1) ? (31 - strm) : strm);
        const int j0 = 4 * blk;
        if (j0 >= M) continue;
        const int j1 = (j0 + 1 < M) ? j0 + 1 : M;   // sentinel redirect
        const int j2 = (j0 + 2 < M) ? j0 + 2 : M;
        const int j3 = (j0 + 3 < M) ? j0 + 3 : M;
        const float4 u0 = sU[j0], u1 = sU[j1], u2 = sU[j2], u3 = sU[j3];
        const float2 b0 = sB[j0], b1 = sB[j1], b2 = sB[j2], b3 = sB[j3];
        const float c0 = -2.f * u0.w, c1 = -2.f * u1.w;
        const float c2 = -2.f * u2.w, c3 = -2.f * u3.w;
        float a0 = 0.f, a1 = 0.f, a2 = 0.f, a3 = 0.f;

        const int t0 = j0 & ~31;               // tile containing j0..j3
        {   // peel tile (predicated)
            const int kk = t0 + lane;
            float4 uk = sU[kk]; float2 bk = sB[kk];
            float d, t, q, P;
            d = fmaf(u0.x, uk.x, fmaf(u0.y, uk.y, u0.z * uk.z));
            t = fmaf(-0.8f, d, 1.0f);
            q = fmaf(c0 * uk.w, d, b0.x + bk.x);
            P = fast_ex2(fmaf(0.6f, fast_lg2(t), fmaf(-0.72134752044448f, q, bk.y)));
            if (kk > j0) a0 = fmaf(P, fc_poly(q), a0);
            d = fmaf(u1.x, uk.x, fmaf(u1.y, uk.y, u1.z * uk.z));
            t = fmaf(-0.8f, d, 1.0f);
            q = fmaf(c1 * uk.w, d, b1.x + bk.x);
            P = fast_ex2(fmaf(0.6f, fast_lg2(t), fmaf(-0.72134752044448f, q, bk.y)));
            if (kk > j1) a1 = fmaf(P, fc_poly(q), a1);
            d = fmaf(u2.x, uk.x, fmaf(u2.y, uk.y, u2.z * uk.z));
            t = fmaf(-0.8f, d, 1.0f);
            q = fmaf(c2 * uk.w, d, b2.x + bk.x);
            P = fast_ex2(fmaf(0.6f, fast_lg2(t), fmaf(-0.72134752044448f, q, bk.y)));
            if (kk > j2) a2 = fmaf(P, fc_poly(q), a2);
            d = fmaf(u3.x, uk.x, fmaf(u3.y, uk.y, u3.z * uk.z));
            t = fmaf(-0.8f, d, 1.0f);
            q = fmaf(c3 * uk.w, d, b3.x + bk.x);
            P = fast_ex2(fmaf(0.6f, fast_lg2(t), fmaf(-0.72134752044448f, q, bk.y)));
            if (kk > j3) a3 = fmaf(P, fc_poly(q), a3);
        }
        // clean tiles
        for (int tt = t0 + 32; tt < Mpad; tt += 32) {
            const int kk = tt + lane;
            float4 uk = sU[kk]; float2 bk = sB[kk];
            float d, t, q, P;
            d = fmaf(u0.x, uk.x, fmaf(u0.y, uk.y, u0.z * uk.z));
            t = fmaf(-0.8f, d, 1.0f);
            q = fmaf(c0 * uk.w, d, b0.x + bk.x);
            P = fast_ex2(fmaf(0.6f, fast_lg2(t), fmaf(-0.72134752044448f, q, bk.y)));
            a0 = fmaf(P, fc_poly(q), a0);
            d = fmaf(u1.x, uk.x, fmaf(u1.y, uk.y, u1.z * uk.z));
            t = fmaf(-0.8f, d, 1.0f);
            q = fmaf(c1 * uk.w, d, b1.x + bk.x);
            P = fast_ex2(fmaf(0.6f, fast_lg2(t), fmaf(-0.72134752044448f, q, bk.y)));
            a1 = fmaf(P, fc_poly(q), a1);
            d = fmaf(u2.x, uk.x, fmaf(u2.y, uk.y, u2.z * uk.z));
            t = fmaf(-0.8f, d, 1.0f);
            q = fmaf(c2 * uk.w, d, b2.x + bk.x);
            P = fast_ex2(fmaf(0.6f, fast_lg2(t), fmaf(-0.72134752044448f, q, bk.y)));
            a2 = fmaf(P, fc_poly(q), a2);
            d = fmaf(u3.x, uk.x, fmaf(u3.y, uk.y, u3.z * uk.z));
            t = fmaf(-0.8f, d, 1.0f);
            q = fmaf(c3 * uk.w, d, b3.x + bk.x);
            P = fast_ex2(fmaf(0.6f, fast_lg2(t), fmaf(-0.72134752044448f, q, bk.y)));
            a3 = fmaf(P, fc_poly(q), a3);
        }
        // row factors a_ij = ex2(lgA_j); sentinel rows give exactly 0
        accw = fmaf(fast_ex2(b0.y), a0, accw);
        accw = fmaf(fast_ex2(b1.y), a1, accw);
        accw = fmaf(fast_ex2(b2.y), a2, accw);
        accw = fmaf(fast_ex2(b3.y), a3, accw);
    }

    accw = warp_sum(accw);
    if (lane == 0) wr[w] = accw;
    __syncthreads();

    // --- publish slice partial; elect last-arriving CTA of this atom ---
    if (tid == 0) {
        float ssum = 0.f;
        #pragma unroll
        for (int q = 0; q < 8; q++) ssum += wr[q];
        g_part[i][sl] = ssum;
        __threadfence();
        int old = atomicAdd(&g_cnt[i], 1);
        int last = (old == NSLICE - 1);
        isLastSh = last;
        if (last) g_cnt[i] = 0;   // reset for next launch / graph replay
    }
    __syncthreads();
    if (!isLastSh) return;

    // --- last CTA: stage weights, deterministic combine, fused MLP ---
    const bool sp = (i == SPECIAL_ATOM);
    const float* W1 = sp ? w1b : w1a;  const float* B1 = sp ? b1b : b1a;
    const float* W2 = sp ? w2b : w2a;  const float* B2 = sp ? b2b : b2a;
    const float* W3 = sp ? w3b : w3a;  const float* B3 = sp ? b3b : b3a;
    for (int t = tid; t < 1841; t += 256) {
        float v;
        if (t < 80)        v = W1[t];
        else if (t < 120)  v = B1[t - 80];
        else if (t < 1760) { int r = (t - 120) / 41, c = (t - 120) - 41 * r;
                             v = (c < 40) ? W2[r * 40 + c] : 0.f; }
        else if (t < 1800) v = B2[t - 1760];
        else if (t < 1840) v = W3[t - 1800];
        else               v = B3[0];
        sW[t] = v;
    }
    if (tid == 0) {
        float s4 = 0.f;
        #pragma unroll
        for (int q = 0; q < NSLICE; q++) s4 += __ldcg(&g_part[i][q]);  // fixed order
        sAng = 1.3195079107728942f * s4;   // 2^(1-ZETA)
    }
    __syncthreads();

    if (tid < 40) {
        float z = fmaf(sW[2 * tid], sAng, fmaf(sW[2 * tid + 1], sRad, sW[80 + tid]));
        sH1[tid] = __fdividef(1.f, fmaf(z, z, 1.f));
    }
    __syncthreads();
    if (tid < 40) {
        float z = sW[1760 + tid];
        const float* row = sW + 120 + tid * 41;
        #pragma unroll 8
        for (int k = 0; k < 40; k++) z = fmaf(row[k], sH1[k], z);
        sH2[tid] = __fdividef(1.f, fmaf(z, z, 1.f));
    }
    __syncthreads();
    if (w == 0) {
        float v = sW[1800 + lane] * sH2[lane];
        if (lane < 8) v = fmaf(sW[1832 + lane], sH2[32 + lane], v);
        v = warp_sum(v);
        if (lane == 0) out[i] = v + sW[1840];
    }
}

extern "C" void kernel_launch(void* const* d_in, const int* in_sizes, int n_in,
                              void* d_out, int out_size) {
    const float* x = (const float*)d_in[0];
    const int N = in_sizes[0] / 3;

    fused_kernel<<<NSLICE * N, 256>>>(
        x, N,
        (const float*)d_in[1],  (const float*)d_in[2],  (const float*)d_in[3],
        (const float*)d_in[4],  (const float*)d_in[5],  (const float*)d_in[6],
        (const float*)d_in[7],  (const float*)d_in[8],  (const float*)d_in[9],
        (const float*)d_in[10], (const float*)d_in[11], (const float*)d_in[12],
        (float*)d_out);
}